// round 3
// baseline (speedup 1.0000x reference)
#include <cuda_runtime.h>
#include <cuda_bf16.h>

// Problem shape (fixed by the dataset): N=100000 nodes, D=128 features.
#define MAXN 100352
#define DF   128

// Scratch (device globals: no allocation allowed in kernel_launch)
__device__ float  g_deg[MAXN];            // degree incl. self loop
__device__ float4 g_u[MAXN * 32];         // u = dis * (x @ W1)   [N,128] as float4
__device__ float4 g_agg[MAXN * 32];       // aggregation accumulator, init = u (self loop)
__device__ float  g_w[MAXN];              // layer-2 per-node scalar w = dis * (h . W2)
__device__ float  g_acc2[MAXN];           // layer-2 accumulator, init = w

// ---------------------------------------------------------------------------
// 1) deg = 1 (self loop)
__global__ void k_init_deg(int n) {
    int i = blockIdx.x * blockDim.x + threadIdx.x;
    if (i < n) g_deg[i] = 1.0f;
}

// 2) deg[dst] += 1 over real edges
__global__ void k_count(const int* __restrict__ dst, int E) {
    int e = blockIdx.x * blockDim.x + threadIdx.x;
    if (e < E) atomicAdd(&g_deg[dst[e]], 1.0f);
}

// ---------------------------------------------------------------------------
// 3) u = dis ⊙ (x @ W1); agg = u  (tiled fp32 GEMM, BM=64, 256 thr, 4x8 micro)
__global__ __launch_bounds__(256) void k_gemm_u(const float* __restrict__ x,
                                                const float* __restrict__ W,
                                                int n) {
    __shared__ float xs[16][64 + 4];   // xs[k][row]  (transposed x tile)
    __shared__ float ws[16][DF];       // ws[k][col]

    int tid = threadIdx.x;
    int tx = tid & 15;        // col group (8 cols)
    int ty = tid >> 4;        // row group (4 rows)
    int row0 = blockIdx.x * 64;

    float acc[4][8];
#pragma unroll
    for (int r = 0; r < 4; r++)
#pragma unroll
        for (int c = 0; c < 8; c++) acc[r][c] = 0.0f;

    // x-load assignment: row rl = tid>>2, k-quad kq = (tid&3)*4
    int rl = tid >> 2;
    int kq = (tid & 3) * 4;
    bool rvalid = (row0 + rl) < n;
    const float* xrow = x + (size_t)(row0 + rl) * DF;

    // W-load assignment: k-row kw = tid>>4, cols c0..c0+7
    int kw = tid >> 4;
    int c0 = (tid & 15) * 8;

    for (int kc = 0; kc < DF; kc += 16) {
        float4 xa = rvalid ? *(const float4*)(xrow + kc + kq)
                           : make_float4(0.f, 0.f, 0.f, 0.f);
        xs[kq + 0][rl] = xa.x;
        xs[kq + 1][rl] = xa.y;
        xs[kq + 2][rl] = xa.z;
        xs[kq + 3][rl] = xa.w;

        const float4* wsrc = (const float4*)(W + (size_t)(kc + kw) * DF + c0);
        float4 w0 = wsrc[0];
        float4 w1 = wsrc[1];
        *(float4*)&ws[kw][c0]     = w0;
        *(float4*)&ws[kw][c0 + 4] = w1;
        __syncthreads();

#pragma unroll
        for (int k = 0; k < 16; k++) {
            float a0 = xs[k][ty * 4 + 0];
            float a1 = xs[k][ty * 4 + 1];
            float a2 = xs[k][ty * 4 + 2];
            float a3 = xs[k][ty * 4 + 3];
            float4 bA = *(float4*)&ws[k][tx * 8];
            float4 bB = *(float4*)&ws[k][tx * 8 + 4];
            float bb[8] = {bA.x, bA.y, bA.z, bA.w, bB.x, bB.y, bB.z, bB.w};
            float aa[4] = {a0, a1, a2, a3};
#pragma unroll
            for (int r = 0; r < 4; r++)
#pragma unroll
                for (int c = 0; c < 8; c++) acc[r][c] = fmaf(aa[r], bb[c], acc[r][c]);
        }
        __syncthreads();
    }

    // Epilogue: scale by dis[row], write u and agg (self-loop init)
#pragma unroll
    for (int r = 0; r < 4; r++) {
        int row = row0 + ty * 4 + r;
        if (row < n) {
            float dis = rsqrtf(g_deg[row]);
            float4 o0 = make_float4(acc[r][0] * dis, acc[r][1] * dis,
                                    acc[r][2] * dis, acc[r][3] * dis);
            float4 o1 = make_float4(acc[r][4] * dis, acc[r][5] * dis,
                                    acc[r][6] * dis, acc[r][7] * dis);
            int base = row * 32 + tx * 2;
            g_u[base]       = o0;
            g_u[base + 1]   = o1;
            g_agg[base]     = o0;
            g_agg[base + 1] = o1;
        }
    }
}

// ---------------------------------------------------------------------------
// 4) agg[dst] += u[src]  — one warp per edge, float4 vector atomics (sm_90+)
__global__ __launch_bounds__(256) void k_scatter1(const int* __restrict__ src,
                                                  const int* __restrict__ dst,
                                                  int E) {
    int w = (int)((blockIdx.x * (unsigned)blockDim.x + threadIdx.x) >> 5);
    int lane = threadIdx.x & 31;
    if (w >= E) return;
    int s = __ldg(&src[w]);
    int d = __ldg(&dst[w]);
    float4 v = g_u[s * 32 + lane];
    atomicAdd(&g_agg[d * 32 + lane], v);
}

// ---------------------------------------------------------------------------
// 5) h = relu(dis*agg + b1); w = dis*(h . W2); acc2 = w   — one warp per node
__global__ __launch_bounds__(256) void k_layer1(const float* __restrict__ b1,
                                                const float* __restrict__ W2,
                                                int n) {
    int node = (int)((blockIdx.x * (unsigned)blockDim.x + threadIdx.x) >> 5);
    int lane = threadIdx.x & 31;
    if (node >= n) return;
    float dis = rsqrtf(g_deg[node]);
    float4 a  = g_agg[node * 32 + lane];
    float4 bb = ((const float4*)b1)[lane];
    float4 w2 = ((const float4*)W2)[lane];
    float h0 = fmaxf(fmaf(dis, a.x, bb.x), 0.0f);
    float h1 = fmaxf(fmaf(dis, a.y, bb.y), 0.0f);
    float h2 = fmaxf(fmaf(dis, a.z, bb.z), 0.0f);
    float h3 = fmaxf(fmaf(dis, a.w, bb.w), 0.0f);
    float part = h0 * w2.x + h1 * w2.y + h2 * w2.z + h3 * w2.w;
#pragma unroll
    for (int o = 16; o; o >>= 1) part += __shfl_xor_sync(0xffffffffu, part, o);
    if (lane == 0) {
        float wv = dis * part;
        g_w[node]    = wv;
        g_acc2[node] = wv;   // self-loop contribution
    }
}

// 6) acc2[dst] += w[src]  (scalar scatter)
__global__ void k_scatter2(const int* __restrict__ src,
                           const int* __restrict__ dst, int E) {
    int e = blockIdx.x * blockDim.x + threadIdx.x;
    if (e < E) atomicAdd(&g_acc2[dst[e]], g_w[src[e]]);
}

// 7) out = dis*acc2 + b2
__global__ void k_final(const float* __restrict__ b2, float* __restrict__ out,
                        int n) {
    int i = blockIdx.x * blockDim.x + threadIdx.x;
    if (i < n) out[i] = fmaf(rsqrtf(g_deg[i]), g_acc2[i], b2[0]);
}

// ---------------------------------------------------------------------------
extern "C" void kernel_launch(void* const* d_in, const int* in_sizes, int n_in,
                              void* d_out, int out_size) {
    const float* x  = (const float*)d_in[0];
    const int*   ei = (const int*)d_in[1];
    const float* W1 = (const float*)d_in[2];
    const float* b1 = (const float*)d_in[3];
    const float* W2 = (const float*)d_in[4];
    const float* b2 = (const float*)d_in[5];
    float* out = (float*)d_out;

    int n = in_sizes[0] / DF;
    int E = in_sizes[1] / 2;
    const int* src = ei;
    const int* dst = ei + E;

    k_init_deg<<<(n + 255) / 256, 256>>>(n);
    k_count<<<(E + 255) / 256, 256>>>(dst, E);
    k_gemm_u<<<(n + 63) / 64, 256>>>(x, W1, n);
    {
        long long threads = (long long)E * 32;
        int blocks = (int)((threads + 255) / 256);
        k_scatter1<<<blocks, 256>>>(src, dst, E);
    }
    {
        long long threads = (long long)n * 32;
        int blocks = (int)((threads + 255) / 256);
        k_layer1<<<blocks, 256>>>(b1, W2, n);
    }
    k_scatter2<<<(E + 255) / 256, 256>>>(src, dst, E);
    k_final<<<(n + 255) / 256, 256>>>(b2, out, n);
}

// round 4
// speedup vs baseline: 1.5304x; 1.5304x over previous
#include <cuda_runtime.h>
#include <cuda_bf16.h>

// Problem shape: N=100000 nodes, D=128 features, E<=1.6M edges.
#define MAXN 100352
#define MAXE 1605632
#define DF   128

// Scratch (device globals: no allocation allowed in kernel_launch)
__device__ int    g_degi[MAXN];        // in-degree (real edges only)
__device__ int    g_rowptr[MAXN];      // exclusive prefix of degi
__device__ int    g_cursor[MAXN];      // fill cursors
__device__ int    g_bsum[256];         // scan block sums
__device__ int    g_boff[256];         // scan block offsets (exclusive)
__device__ int    g_csr[MAXE];         // src ids sorted by dst
__device__ float4 g_u[MAXN * 32];      // u = dis * (x @ W1)   [N,128] as float4
__device__ float  g_w[MAXN];           // layer-2 per-node scalar w = dis*(h . W2)

// ---------------------------------------------------------------------------
// CSR build
__global__ void k_zero_deg(int n) {
    int i = blockIdx.x * blockDim.x + threadIdx.x;
    if (i < n) g_degi[i] = 0;
}

__global__ void k_count(const int* __restrict__ dst, int E) {
    int e = blockIdx.x * blockDim.x + threadIdx.x;
    if (e < E) atomicAdd(&g_degi[dst[e]], 1);
}

// Per-block exclusive scan of 512 elements (512 threads)
__global__ __launch_bounds__(512) void k_scanA(int n) {
    __shared__ int s[512];
    int i = blockIdx.x * 512 + threadIdx.x;
    int v = (i < n) ? g_degi[i] : 0;
    s[threadIdx.x] = v;
    __syncthreads();
#pragma unroll
    for (int o = 1; o < 512; o <<= 1) {
        int t = (threadIdx.x >= o) ? s[threadIdx.x - o] : 0;
        __syncthreads();
        s[threadIdx.x] += t;
        __syncthreads();
    }
    if (i < n) g_rowptr[i] = s[threadIdx.x] - v;   // exclusive within block
    if (threadIdx.x == 511) g_bsum[blockIdx.x] = s[511];
}

// Single-block exclusive scan of block sums
__global__ __launch_bounds__(256) void k_scanB(int nb) {
    __shared__ int s[256];
    int v = (threadIdx.x < nb) ? g_bsum[threadIdx.x] : 0;
    s[threadIdx.x] = v;
    __syncthreads();
#pragma unroll
    for (int o = 1; o < 256; o <<= 1) {
        int t = (threadIdx.x >= o) ? s[threadIdx.x - o] : 0;
        __syncthreads();
        s[threadIdx.x] += t;
        __syncthreads();
    }
    g_boff[threadIdx.x] = s[threadIdx.x] - v;
}

__global__ void k_scanC(int n) {
    int i = blockIdx.x * blockDim.x + threadIdx.x;
    if (i < n) {
        int r = g_rowptr[i] + g_boff[i >> 9];
        g_rowptr[i] = r;
        g_cursor[i] = r;
    }
}

__global__ void k_fill(const int* __restrict__ src, const int* __restrict__ dst,
                       int E) {
    int e = blockIdx.x * blockDim.x + threadIdx.x;
    if (e < E) {
        int pos = atomicAdd(&g_cursor[dst[e]], 1);
        g_csr[pos] = src[e];
    }
}

// ---------------------------------------------------------------------------
// u = dis ⊙ (x @ W1)  (tiled fp32 GEMM, BM=64, 256 thr, 4x8 micro)
__global__ __launch_bounds__(256) void k_gemm_u(const float* __restrict__ x,
                                                const float* __restrict__ W,
                                                int n) {
    __shared__ float xs[16][64 + 4];   // xs[k][row]  (transposed x tile)
    __shared__ float ws[16][DF];       // ws[k][col]

    int tid = threadIdx.x;
    int tx = tid & 15;        // col group (8 cols)
    int ty = tid >> 4;        // row group (4 rows)
    int row0 = blockIdx.x * 64;

    float acc[4][8];
#pragma unroll
    for (int r = 0; r < 4; r++)
#pragma unroll
        for (int c = 0; c < 8; c++) acc[r][c] = 0.0f;

    int rl = tid >> 2;
    int kq = (tid & 3) * 4;
    bool rvalid = (row0 + rl) < n;
    const float* xrow = x + (size_t)(row0 + rl) * DF;

    int kw = tid >> 4;
    int c0 = (tid & 15) * 8;

    for (int kc = 0; kc < DF; kc += 16) {
        float4 xa = rvalid ? *(const float4*)(xrow + kc + kq)
                           : make_float4(0.f, 0.f, 0.f, 0.f);
        xs[kq + 0][rl] = xa.x;
        xs[kq + 1][rl] = xa.y;
        xs[kq + 2][rl] = xa.z;
        xs[kq + 3][rl] = xa.w;

        const float4* wsrc = (const float4*)(W + (size_t)(kc + kw) * DF + c0);
        float4 w0 = wsrc[0];
        float4 w1 = wsrc[1];
        *(float4*)&ws[kw][c0]     = w0;
        *(float4*)&ws[kw][c0 + 4] = w1;
        __syncthreads();

#pragma unroll
        for (int k = 0; k < 16; k++) {
            float aa[4] = {xs[k][ty * 4 + 0], xs[k][ty * 4 + 1],
                           xs[k][ty * 4 + 2], xs[k][ty * 4 + 3]};
            float4 bA = *(float4*)&ws[k][tx * 8];
            float4 bB = *(float4*)&ws[k][tx * 8 + 4];
            float bb[8] = {bA.x, bA.y, bA.z, bA.w, bB.x, bB.y, bB.z, bB.w};
#pragma unroll
            for (int r = 0; r < 4; r++)
#pragma unroll
                for (int c = 0; c < 8; c++) acc[r][c] = fmaf(aa[r], bb[c], acc[r][c]);
        }
        __syncthreads();
    }

#pragma unroll
    for (int r = 0; r < 4; r++) {
        int row = row0 + ty * 4 + r;
        if (row < n) {
            float dis = rsqrtf((float)(g_degi[row] + 1));
            float4 o0 = make_float4(acc[r][0] * dis, acc[r][1] * dis,
                                    acc[r][2] * dis, acc[r][3] * dis);
            float4 o1 = make_float4(acc[r][4] * dis, acc[r][5] * dis,
                                    acc[r][6] * dis, acc[r][7] * dis);
            int base = row * 32 + tx * 2;
            g_u[base]     = o0;
            g_u[base + 1] = o1;
        }
    }
}

// ---------------------------------------------------------------------------
// Fused: agg = u[node] + Σ u[csr]; h = relu(dis*agg + b1); w = dis*(h.W2)
// One warp per node, register accumulation, no atomics.
__global__ __launch_bounds__(256) void k_agg1(const float* __restrict__ b1,
                                              const float* __restrict__ W2,
                                              int n) {
    int node = (int)((blockIdx.x * (unsigned)blockDim.x + threadIdx.x) >> 5);
    int lane = threadIdx.x & 31;
    if (node >= n) return;

    int row  = g_rowptr[node];
    int degv = g_degi[node];

    float4 a = g_u[node * 32 + lane];   // self-loop term

    for (int base = 0; base < degv; base += 32) {
        int e = base + lane;
        int sv = (e < degv) ? g_csr[row + e] : 0;
        int m = degv - base;
        if (m > 32) m = 32;
#pragma unroll 4
        for (int j = 0; j < m; j++) {
            int s = __shfl_sync(0xffffffffu, sv, j);
            float4 v = g_u[s * 32 + lane];
            a.x += v.x; a.y += v.y; a.z += v.z; a.w += v.w;
        }
    }

    float dis = rsqrtf((float)(degv + 1));
    float4 bb = __ldg(&((const float4*)b1)[lane]);
    float4 w2 = __ldg(&((const float4*)W2)[lane]);
    float h0 = fmaxf(fmaf(dis, a.x, bb.x), 0.0f);
    float h1 = fmaxf(fmaf(dis, a.y, bb.y), 0.0f);
    float h2 = fmaxf(fmaf(dis, a.z, bb.z), 0.0f);
    float h3 = fmaxf(fmaf(dis, a.w, bb.w), 0.0f);
    float part = h0 * w2.x + h1 * w2.y + h2 * w2.z + h3 * w2.w;
#pragma unroll
    for (int o = 16; o; o >>= 1) part += __shfl_xor_sync(0xffffffffu, part, o);
    if (lane == 0) g_w[node] = dis * part;
}

// ---------------------------------------------------------------------------
// Fused layer-2 aggregation + bias: out = dis*(w[node] + Σ w[csr]) + b2
__global__ __launch_bounds__(256) void k_agg2(const float* __restrict__ b2,
                                              float* __restrict__ out, int n) {
    int node = (int)((blockIdx.x * (unsigned)blockDim.x + threadIdx.x) >> 5);
    int lane = threadIdx.x & 31;
    if (node >= n) return;

    int row  = g_rowptr[node];
    int degv = g_degi[node];

    float part = 0.0f;
    for (int e = lane; e < degv; e += 32) part += g_w[g_csr[row + e]];
#pragma unroll
    for (int o = 16; o; o >>= 1) part += __shfl_xor_sync(0xffffffffu, part, o);

    if (lane == 0) {
        float dis = rsqrtf((float)(degv + 1));
        out[node] = fmaf(dis, g_w[node] + part, b2[0]);
    }
}

// ---------------------------------------------------------------------------
extern "C" void kernel_launch(void* const* d_in, const int* in_sizes, int n_in,
                              void* d_out, int out_size) {
    const float* x  = (const float*)d_in[0];
    const int*   ei = (const int*)d_in[1];
    const float* W1 = (const float*)d_in[2];
    const float* b1 = (const float*)d_in[3];
    const float* W2 = (const float*)d_in[4];
    const float* b2 = (const float*)d_in[5];
    float* out = (float*)d_out;

    int n = in_sizes[0] / DF;
    int E = in_sizes[1] / 2;
    const int* src = ei;
    const int* dst = ei + E;

    int nb = (n + 511) / 512;   // scan blocks (<=256)

    k_zero_deg<<<(n + 255) / 256, 256>>>(n);
    k_count<<<(E + 255) / 256, 256>>>(dst, E);
    k_scanA<<<nb, 512>>>(n);
    k_scanB<<<1, 256>>>(nb);
    k_scanC<<<(n + 255) / 256, 256>>>(n);
    k_fill<<<(E + 255) / 256, 256>>>(src, dst, E);

    k_gemm_u<<<(n + 63) / 64, 256>>>(x, W1, n);

    {
        long long threads = (long long)n * 32;
        int blocks = (int)((threads + 255) / 256);
        k_agg1<<<blocks, 256>>>(b1, W2, n);
        k_agg2<<<blocks, 256>>>(b2, out, n);
    }
}

// round 6
// speedup vs baseline: 2.0005x; 1.3072x over previous
#include <cuda_runtime.h>
#include <cuda_bf16.h>
#include <cstdint>

// Problem shape: N=100000 nodes, D=128 features, E<=1.6M edges.
#define MAXN 100352
#define MAXE 1605632
#define DF   128

// Scratch (device globals: no allocation allowed in kernel_launch)
__device__ int    g_degi[MAXN];        // in-degree (real edges only)
__device__ int    g_rowptr[MAXN];      // exclusive prefix of degi
__device__ int    g_cursor[MAXN];      // fill cursors
__device__ int    g_bsum[256];         // scan block sums
__device__ int    g_boff[256];         // scan block offsets (exclusive)
__device__ int    g_csr[MAXE];         // src ids sorted by dst
__device__ float4 g_u[MAXN * 32];      // u = dis * (x @ W1)   [N,128] as float4
__device__ float  g_w[MAXN];           // layer-2 per-node scalar w = dis*(h . W2)
__device__ __nv_bfloat16 g_bh[DF * DF];  // W1 hi (bf16), natural [k][n]
__device__ __nv_bfloat16 g_bl[DF * DF];  // W1 lo (bf16), natural [k][n]

// ---------------------------------------------------------------------------
// mma.sync / ldmatrix helpers (portable sm_80+ PTX; compiles for compute_103)
__device__ __forceinline__ uint32_t smem_to_u32(const void* p) {
    uint32_t a;
    asm("{ .reg .u64 t; cvta.to.shared.u64 t, %1; cvt.u32.u64 %0, t; }"
        : "=r"(a) : "l"(p));
    return a;
}
__device__ __forceinline__ void ldsm_x4(uint32_t* r, uint32_t addr) {
    asm volatile("ldmatrix.sync.aligned.m8n8.x4.shared.b16 {%0,%1,%2,%3}, [%4];"
                 : "=r"(r[0]), "=r"(r[1]), "=r"(r[2]), "=r"(r[3]) : "r"(addr));
}
__device__ __forceinline__ void ldsm_x4t(uint32_t* r, uint32_t addr) {
    asm volatile("ldmatrix.sync.aligned.m8n8.x4.trans.shared.b16 {%0,%1,%2,%3}, [%4];"
                 : "=r"(r[0]), "=r"(r[1]), "=r"(r[2]), "=r"(r[3]) : "r"(addr));
}
__device__ __forceinline__ void mma16816(float* c, const uint32_t* a,
                                         uint32_t b0, uint32_t b1) {
    asm volatile(
        "mma.sync.aligned.m16n8k16.row.col.f32.bf16.bf16.f32 "
        "{%0,%1,%2,%3}, {%4,%5,%6,%7}, {%8,%9}, {%0,%1,%2,%3};"
        : "+f"(c[0]), "+f"(c[1]), "+f"(c[2]), "+f"(c[3])
        : "r"(a[0]), "r"(a[1]), "r"(a[2]), "r"(a[3]), "r"(b0), "r"(b1));
}

// SMEM layout for the GEMM (bf16, padded stride 136 elems = 272B, 16B aligned,
// conflict-free ldmatrix: bank start of row r = (4r) mod 32)
#define LDS_STRIDE 136
#define TILE_BYTES (128 * LDS_STRIDE * 2)   // 34816
#define OFF_AHI 0
#define OFF_ALO TILE_BYTES
#define OFF_BHI (2 * TILE_BYTES)
#define OFF_BLO (3 * TILE_BYTES)
#define GSMEM_TOTAL (4 * TILE_BYTES)        // 139264

// ---------------------------------------------------------------------------
// CSR build
__global__ void k_zero_deg(int n) {
    int i = blockIdx.x * blockDim.x + threadIdx.x;
    if (i < n) g_degi[i] = 0;
}
__global__ void k_count(const int* __restrict__ dst, int E) {
    int e = blockIdx.x * blockDim.x + threadIdx.x;
    if (e < E) atomicAdd(&g_degi[dst[e]], 1);
}
__global__ __launch_bounds__(512) void k_scanA(int n) {
    __shared__ int s[512];
    int i = blockIdx.x * 512 + threadIdx.x;
    int v = (i < n) ? g_degi[i] : 0;
    s[threadIdx.x] = v;
    __syncthreads();
#pragma unroll
    for (int o = 1; o < 512; o <<= 1) {
        int t = (threadIdx.x >= o) ? s[threadIdx.x - o] : 0;
        __syncthreads();
        s[threadIdx.x] += t;
        __syncthreads();
    }
    if (i < n) g_rowptr[i] = s[threadIdx.x] - v;
    if (threadIdx.x == 511) g_bsum[blockIdx.x] = s[511];
}
__global__ __launch_bounds__(256) void k_scanB(int nb) {
    __shared__ int s[256];
    int v = (threadIdx.x < nb) ? g_bsum[threadIdx.x] : 0;
    s[threadIdx.x] = v;
    __syncthreads();
#pragma unroll
    for (int o = 1; o < 256; o <<= 1) {
        int t = (threadIdx.x >= o) ? s[threadIdx.x - o] : 0;
        __syncthreads();
        s[threadIdx.x] += t;
        __syncthreads();
    }
    g_boff[threadIdx.x] = s[threadIdx.x] - v;
}
__global__ void k_scanC(int n) {
    int i = blockIdx.x * blockDim.x + threadIdx.x;
    if (i < n) {
        int r = g_rowptr[i] + g_boff[i >> 9];
        g_rowptr[i] = r;
        g_cursor[i] = r;
    }
}
__global__ void k_fill(const int* __restrict__ src, const int* __restrict__ dst,
                       int E) {
    int e = blockIdx.x * blockDim.x + threadIdx.x;
    if (e < E) {
        int pos = atomicAdd(&g_cursor[dst[e]], 1);
        g_csr[pos] = src[e];
    }
}

// ---------------------------------------------------------------------------
// W1 -> bf16 hi/lo split in natural [k][n] layout
__global__ void k_prep_w(const float* __restrict__ W1) {
    int i = blockIdx.x * blockDim.x + threadIdx.x;
    if (i < DF * DF) {
        float v = W1[i];
        __nv_bfloat16 h = __float2bfloat16(v);
        g_bh[i] = h;
        g_bl[i] = __float2bfloat16(v - __bfloat162float(h));
    }
}

// ---------------------------------------------------------------------------
// u = dis * (x @ W1) via split-bf16 mma.sync (3 products, fp32 accum).
// CTA: 128 rows, 256 threads = 8 warps (4 m-warps x 2 n-warps; 32x64 per warp).
__global__ __launch_bounds__(256) void k_gemm_u(const float* __restrict__ x,
                                                int n) {
    extern __shared__ char smem[];
    uint32_t sb = smem_to_u32(smem);
    int tid = threadIdx.x;
    int lane = tid & 31;
    int wid = tid >> 5;
    int row0 = blockIdx.x * 128;

    // --- Stage A: load x rows, convert fp32 -> bf16 hi/lo into SMEM [m][136]
    {
        int r = tid >> 1;             // 0..127
        int half = tid & 1;           // 16 float4 per half row
        int row = row0 + r;
        bool rv = row < n;
        const float4* xr = (const float4*)(x + (size_t)row * DF) + half * 16;
        char* ah = smem + OFF_AHI + (size_t)(r * LDS_STRIDE + half * 64) * 2;
        char* al = smem + OFF_ALO + (size_t)(r * LDS_STRIDE + half * 64) * 2;
#pragma unroll
        for (int j = 0; j < 16; j++) {
            float4 v = rv ? xr[j] : make_float4(0.f, 0.f, 0.f, 0.f);
            __nv_bfloat16 h0 = __float2bfloat16(v.x);
            __nv_bfloat16 h1 = __float2bfloat16(v.y);
            __nv_bfloat16 h2 = __float2bfloat16(v.z);
            __nv_bfloat16 h3 = __float2bfloat16(v.w);
            uint32_t hp0 = (uint32_t)__bfloat16_as_ushort(h0) |
                           ((uint32_t)__bfloat16_as_ushort(h1) << 16);
            uint32_t hp1 = (uint32_t)__bfloat16_as_ushort(h2) |
                           ((uint32_t)__bfloat16_as_ushort(h3) << 16);
            __nv_bfloat16 l0 = __float2bfloat16(v.x - __bfloat162float(h0));
            __nv_bfloat16 l1 = __float2bfloat16(v.y - __bfloat162float(h1));
            __nv_bfloat16 l2 = __float2bfloat16(v.z - __bfloat162float(h2));
            __nv_bfloat16 l3 = __float2bfloat16(v.w - __bfloat162float(h3));
            uint32_t lp0 = (uint32_t)__bfloat16_as_ushort(l0) |
                           ((uint32_t)__bfloat16_as_ushort(l1) << 16);
            uint32_t lp1 = (uint32_t)__bfloat16_as_ushort(l2) |
                           ((uint32_t)__bfloat16_as_ushort(l3) << 16);
            *(uint2*)(ah + j * 8) = make_uint2(hp0, hp1);
            *(uint2*)(al + j * 8) = make_uint2(lp0, lp1);
        }
    }
    // --- Stage B: copy precomputed W1 hi/lo into SMEM [k][136]
    {
        int k = tid >> 1;
        int half = tid & 1;
        const uint4* bh = (const uint4*)(g_bh + k * DF + half * 64);
        const uint4* bl = (const uint4*)(g_bl + k * DF + half * 64);
        char* dh = smem + OFF_BHI + (size_t)(k * LDS_STRIDE + half * 64) * 2;
        char* dl = smem + OFF_BLO + (size_t)(k * LDS_STRIDE + half * 64) * 2;
#pragma unroll
        for (int j = 0; j < 8; j++) {
            *((uint4*)dh + j) = bh[j];
            *((uint4*)dl + j) = bl[j];
        }
    }
    __syncthreads();

    // --- Compute: per warp 2 m-tiles (m16) x 8 n-tiles (n8), K=128 ---
    int wm = wid >> 1;
    int wn = wid & 1;
    uint32_t aBase = sb + OFF_AHI +
        (uint32_t)(((wm * 32 + (lane & 7) + ((lane >> 3) & 1) * 8) * LDS_STRIDE +
                    ((lane >> 4) << 3)) * 2);
    uint32_t aBase1 = aBase + 16 * LDS_STRIDE * 2;
    uint32_t bBase = sb + OFF_BHI +
        (uint32_t)((((lane & 7) + ((lane >> 3) & 1) * 8) * LDS_STRIDE +
                    wn * 64 + ((lane >> 4) << 3)) * 2);

    float acc[2][8][4];
#pragma unroll
    for (int mt = 0; mt < 2; mt++)
#pragma unroll
        for (int nt = 0; nt < 8; nt++)
#pragma unroll
            for (int i = 0; i < 4; i++) acc[mt][nt][i] = 0.0f;

#pragma unroll 1
    for (int p = 0; p < 3; p++) {
        uint32_t aOff = (p == 1) ? (uint32_t)TILE_BYTES : 0u;   // A_lo for p=1
        uint32_t bOff = (p == 2) ? (uint32_t)TILE_BYTES : 0u;   // B_lo for p=2
#pragma unroll 1
        for (int kk = 0; kk < 8; kk++) {
            uint32_t a0[4], a1[4];
            ldsm_x4(a0, aBase + aOff + kk * 32);
            ldsm_x4(a1, aBase1 + aOff + kk * 32);
#pragma unroll
            for (int g = 0; g < 4; g++) {
                uint32_t b[4];
                ldsm_x4t(b, bBase + bOff + kk * (16 * LDS_STRIDE * 2) + g * 32);
                mma16816(acc[0][2 * g],     a0, b[0], b[1]);
                mma16816(acc[0][2 * g + 1], a0, b[2], b[3]);
                mma16816(acc[1][2 * g],     a1, b[0], b[1]);
                mma16816(acc[1][2 * g + 1], a1, b[2], b[3]);
            }
        }
    }

    // --- Epilogue: scale by dis[row], store float2 pairs directly ---
    float* gf = (float*)g_u;
#pragma unroll
    for (int mt = 0; mt < 2; mt++) {
        int r0 = row0 + wm * 32 + mt * 16 + (lane >> 2);
        int r1 = r0 + 8;
        float dis0 = (r0 < n) ? rsqrtf((float)(g_degi[r0] + 1)) : 0.0f;
        float dis1 = (r1 < n) ? rsqrtf((float)(g_degi[r1] + 1)) : 0.0f;
        int colb = wn * 64 + (lane & 3) * 2;
#pragma unroll
        for (int nt = 0; nt < 8; nt++) {
            int col = colb + nt * 8;
            if (r0 < n)
                *(float2*)(gf + (size_t)r0 * DF + col) =
                    make_float2(acc[mt][nt][0] * dis0, acc[mt][nt][1] * dis0);
            if (r1 < n)
                *(float2*)(gf + (size_t)r1 * DF + col) =
                    make_float2(acc[mt][nt][2] * dis1, acc[mt][nt][3] * dis1);
        }
    }
}

// ---------------------------------------------------------------------------
// Fused: agg = u[node] + sum u[csr]; h = relu(dis*agg + b1); w = dis*(h.W2)
__global__ __launch_bounds__(256) void k_agg1(const float* __restrict__ b1,
                                              const float* __restrict__ W2,
                                              int n) {
    int node = (int)((blockIdx.x * (unsigned)blockDim.x + threadIdx.x) >> 5);
    int lane = threadIdx.x & 31;
    if (node >= n) return;

    int row  = g_rowptr[node];
    int degv = g_degi[node];

    float4 a = g_u[node * 32 + lane];   // self-loop term

    for (int base = 0; base < degv; base += 32) {
        int e = base + lane;
        int sv = (e < degv) ? g_csr[row + e] : 0;
        int m = degv - base;
        if (m > 32) m = 32;
#pragma unroll 4
        for (int j = 0; j < m; j++) {
            int s = __shfl_sync(0xffffffffu, sv, j);
            float4 v = g_u[s * 32 + lane];
            a.x += v.x; a.y += v.y; a.z += v.z; a.w += v.w;
        }
    }

    float dis = rsqrtf((float)(degv + 1));
    float4 bb = __ldg(&((const float4*)b1)[lane]);
    float4 w2 = __ldg(&((const float4*)W2)[lane]);
    float h0 = fmaxf(fmaf(dis, a.x, bb.x), 0.0f);
    float h1 = fmaxf(fmaf(dis, a.y, bb.y), 0.0f);
    float h2 = fmaxf(fmaf(dis, a.z, bb.z), 0.0f);
    float h3 = fmaxf(fmaf(dis, a.w, bb.w), 0.0f);
    float part = h0 * w2.x + h1 * w2.y + h2 * w2.z + h3 * w2.w;
#pragma unroll
    for (int o = 16; o; o >>= 1) part += __shfl_xor_sync(0xffffffffu, part, o);
    if (lane == 0) g_w[node] = dis * part;
}

// ---------------------------------------------------------------------------
// Fused layer-2 aggregation + bias
__global__ __launch_bounds__(256) void k_agg2(const float* __restrict__ b2,
                                              float* __restrict__ out, int n) {
    int node = (int)((blockIdx.x * (unsigned)blockDim.x + threadIdx.x) >> 5);
    int lane = threadIdx.x & 31;
    if (node >= n) return;

    int row  = g_rowptr[node];
    int degv = g_degi[node];

    float part = 0.0f;
    for (int e = lane; e < degv; e += 32) part += g_w[g_csr[row + e]];
#pragma unroll
    for (int o = 16; o; o >>= 1) part += __shfl_xor_sync(0xffffffffu, part, o);

    if (lane == 0) {
        float dis = rsqrtf((float)(degv + 1));
        out[node] = fmaf(dis, g_w[node] + part, b2[0]);
    }
}

// ---------------------------------------------------------------------------
extern "C" void kernel_launch(void* const* d_in, const int* in_sizes, int n_in,
                              void* d_out, int out_size) {
    const float* x  = (const float*)d_in[0];
    const int*   ei = (const int*)d_in[1];
    const float* W1 = (const float*)d_in[2];
    const float* b1 = (const float*)d_in[3];
    const float* W2 = (const float*)d_in[4];
    const float* b2 = (const float*)d_in[5];
    float* out = (float*)d_out;

    int n = in_sizes[0] / DF;
    int E = in_sizes[1] / 2;
    const int* src = ei;
    const int* dst = ei + E;

    int nb = (n + 511) / 512;

    cudaFuncSetAttribute(k_gemm_u, cudaFuncAttributeMaxDynamicSharedMemorySize,
                         GSMEM_TOTAL);

    k_zero_deg<<<(n + 255) / 256, 256>>>(n);
    k_count<<<(E + 255) / 256, 256>>>(dst, E);
    k_scanA<<<nb, 512>>>(n);
    k_scanB<<<1, 256>>>(nb);
    k_scanC<<<(n + 255) / 256, 256>>>(n);
    k_fill<<<(E + 255) / 256, 256>>>(src, dst, E);

    k_prep_w<<<(DF * DF + 255) / 256, 256>>>(W1);
    k_gemm_u<<<(n + 127) / 128, 256, GSMEM_TOTAL>>>(x, n);

    {
        long long threads = (long long)n * 32;
        int blocks = (int)((threads + 255) / 256);
        k_agg1<<<blocks, 256>>>(b1, W2, n);
        k_agg2<<<blocks, 256>>>(b2, out, n);
    }
}

// round 7
// speedup vs baseline: 2.0465x; 1.0230x over previous
#include <cuda_runtime.h>
#include <cuda_bf16.h>
#include <cuda_fp16.h>
#include <cstdint>

// Problem shape: N=100000 nodes, D=128 features, E<=1.6M edges.
#define MAXN 100352
#define MAXE 1605632
#define DF   128

// Scratch (device globals: no allocation allowed in kernel_launch)
__device__ int    g_degi[MAXN];        // in-degree (real edges only)
__device__ int    g_rowptr[MAXN];      // exclusive prefix of degi
__device__ int    g_cursor[MAXN];      // fill cursors
__device__ int    g_bsum[256];         // scan block sums
__device__ int    g_boff[256];         // scan block offsets (exclusive)
__device__ int    g_csr[MAXE];         // src ids sorted by dst
__device__ __half g_uh[MAXN * DF];     // u = dis * (x @ W1)  (fp16)
__device__ float  g_w[MAXN];           // layer-2 per-node scalar w = dis*(h . W2)
__device__ __nv_bfloat16 g_bh[DF * DF];  // W1 hi (bf16), natural [k][n]
__device__ __nv_bfloat16 g_bl[DF * DF];  // W1 lo (bf16), natural [k][n]

// ---------------------------------------------------------------------------
// mma.sync / ldmatrix helpers (portable sm_80+ PTX)
__device__ __forceinline__ uint32_t smem_to_u32(const void* p) {
    uint32_t a;
    asm("{ .reg .u64 t; cvta.to.shared.u64 t, %1; cvt.u32.u64 %0, t; }"
        : "=r"(a) : "l"(p));
    return a;
}
__device__ __forceinline__ void ldsm_x4(uint32_t* r, uint32_t addr) {
    asm volatile("ldmatrix.sync.aligned.m8n8.x4.shared.b16 {%0,%1,%2,%3}, [%4];"
                 : "=r"(r[0]), "=r"(r[1]), "=r"(r[2]), "=r"(r[3]) : "r"(addr));
}
__device__ __forceinline__ void ldsm_x4t(uint32_t* r, uint32_t addr) {
    asm volatile("ldmatrix.sync.aligned.m8n8.x4.trans.shared.b16 {%0,%1,%2,%3}, [%4];"
                 : "=r"(r[0]), "=r"(r[1]), "=r"(r[2]), "=r"(r[3]) : "r"(addr));
}
__device__ __forceinline__ void mma16816(float* c, const uint32_t* a,
                                         uint32_t b0, uint32_t b1) {
    asm volatile(
        "mma.sync.aligned.m16n8k16.row.col.f32.bf16.bf16.f32 "
        "{%0,%1,%2,%3}, {%4,%5,%6,%7}, {%8,%9}, {%0,%1,%2,%3};"
        : "+f"(c[0]), "+f"(c[1]), "+f"(c[2]), "+f"(c[3])
        : "r"(a[0]), "r"(a[1]), "r"(a[2]), "r"(a[3]), "r"(b0), "r"(b1));
}

// SMEM layout for the GEMM (bf16, padded stride 136 elems)
#define LDS_STRIDE 136
#define TILE_BYTES (128 * LDS_STRIDE * 2)   // 34816
#define OFF_AHI 0
#define OFF_ALO TILE_BYTES
#define OFF_BHI (2 * TILE_BYTES)
#define OFF_BLO (3 * TILE_BYTES)
#define GSMEM_TOTAL (4 * TILE_BYTES)        // 139264

// ---------------------------------------------------------------------------
// CSR build
__global__ void k_zero_deg(int n) {
    int i = blockIdx.x * blockDim.x + threadIdx.x;
    if (i < n) g_degi[i] = 0;
}
__global__ void k_count(const int* __restrict__ dst, int E) {
    int e = blockIdx.x * blockDim.x + threadIdx.x;
    if (e < E) atomicAdd(&g_degi[dst[e]], 1);
}
__global__ __launch_bounds__(512) void k_scanA(int n) {
    __shared__ int s[512];
    int i = blockIdx.x * 512 + threadIdx.x;
    int v = (i < n) ? g_degi[i] : 0;
    s[threadIdx.x] = v;
    __syncthreads();
#pragma unroll
    for (int o = 1; o < 512; o <<= 1) {
        int t = (threadIdx.x >= o) ? s[threadIdx.x - o] : 0;
        __syncthreads();
        s[threadIdx.x] += t;
        __syncthreads();
    }
    if (i < n) g_rowptr[i] = s[threadIdx.x] - v;
    if (threadIdx.x == 511) g_bsum[blockIdx.x] = s[511];
}
__global__ __launch_bounds__(256) void k_scanB(int nb) {
    __shared__ int s[256];
    int v = (threadIdx.x < nb) ? g_bsum[threadIdx.x] : 0;
    s[threadIdx.x] = v;
    __syncthreads();
#pragma unroll
    for (int o = 1; o < 256; o <<= 1) {
        int t = (threadIdx.x >= o) ? s[threadIdx.x - o] : 0;
        __syncthreads();
        s[threadIdx.x] += t;
        __syncthreads();
    }
    g_boff[threadIdx.x] = s[threadIdx.x] - v;
}
__global__ void k_scanC(int n) {
    int i = blockIdx.x * blockDim.x + threadIdx.x;
    if (i < n) {
        int r = g_rowptr[i] + g_boff[i >> 9];
        g_rowptr[i] = r;
        g_cursor[i] = r;
    }
}
__global__ void k_fill(const int* __restrict__ src, const int* __restrict__ dst,
                       int E) {
    int e = blockIdx.x * blockDim.x + threadIdx.x;
    if (e < E) {
        int pos = atomicAdd(&g_cursor[dst[e]], 1);
        g_csr[pos] = src[e];
    }
}

// ---------------------------------------------------------------------------
// W1 -> bf16 hi/lo split in natural [k][n] layout
__global__ void k_prep_w(const float* __restrict__ W1) {
    int i = blockIdx.x * blockDim.x + threadIdx.x;
    if (i < DF * DF) {
        float v = W1[i];
        __nv_bfloat16 h = __float2bfloat16(v);
        g_bh[i] = h;
        g_bl[i] = __float2bfloat16(v - __bfloat162float(h));
    }
}

// ---------------------------------------------------------------------------
// u = dis * (x @ W1) via split-bf16 mma.sync (3 products, fp32 accum),
// epilogue stores fp16. CTA: 128 rows, 256 threads / 8 warps (4x2).
__global__ __launch_bounds__(256) void k_gemm_u(const float* __restrict__ x,
                                                int n) {
    extern __shared__ char smem[];
    uint32_t sb = smem_to_u32(smem);
    int tid = threadIdx.x;
    int lane = tid & 31;
    int wid = tid >> 5;
    int row0 = blockIdx.x * 128;

    // --- Stage A: x rows -> bf16 hi/lo into SMEM [m][136]
    {
        int r = tid >> 1;
        int half = tid & 1;
        int row = row0 + r;
        bool rv = row < n;
        const float4* xr = (const float4*)(x + (size_t)row * DF) + half * 16;
        char* ah = smem + OFF_AHI + (size_t)(r * LDS_STRIDE + half * 64) * 2;
        char* al = smem + OFF_ALO + (size_t)(r * LDS_STRIDE + half * 64) * 2;
#pragma unroll
        for (int j = 0; j < 16; j++) {
            float4 v = rv ? xr[j] : make_float4(0.f, 0.f, 0.f, 0.f);
            __nv_bfloat16 h0 = __float2bfloat16(v.x);
            __nv_bfloat16 h1 = __float2bfloat16(v.y);
            __nv_bfloat16 h2 = __float2bfloat16(v.z);
            __nv_bfloat16 h3 = __float2bfloat16(v.w);
            uint32_t hp0 = (uint32_t)__bfloat16_as_ushort(h0) |
                           ((uint32_t)__bfloat16_as_ushort(h1) << 16);
            uint32_t hp1 = (uint32_t)__bfloat16_as_ushort(h2) |
                           ((uint32_t)__bfloat16_as_ushort(h3) << 16);
            __nv_bfloat16 l0 = __float2bfloat16(v.x - __bfloat162float(h0));
            __nv_bfloat16 l1 = __float2bfloat16(v.y - __bfloat162float(h1));
            __nv_bfloat16 l2 = __float2bfloat16(v.z - __bfloat162float(h2));
            __nv_bfloat16 l3 = __float2bfloat16(v.w - __bfloat162float(h3));
            uint32_t lp0 = (uint32_t)__bfloat16_as_ushort(l0) |
                           ((uint32_t)__bfloat16_as_ushort(l1) << 16);
            uint32_t lp1 = (uint32_t)__bfloat16_as_ushort(l2) |
                           ((uint32_t)__bfloat16_as_ushort(l3) << 16);
            *(uint2*)(ah + j * 8) = make_uint2(hp0, hp1);
            *(uint2*)(al + j * 8) = make_uint2(lp0, lp1);
        }
    }
    // --- Stage B: precomputed W1 hi/lo into SMEM [k][136]
    {
        int k = tid >> 1;
        int half = tid & 1;
        const uint4* bh = (const uint4*)(g_bh + k * DF + half * 64);
        const uint4* bl = (const uint4*)(g_bl + k * DF + half * 64);
        char* dh = smem + OFF_BHI + (size_t)(k * LDS_STRIDE + half * 64) * 2;
        char* dl = smem + OFF_BLO + (size_t)(k * LDS_STRIDE + half * 64) * 2;
#pragma unroll
        for (int j = 0; j < 8; j++) {
            *((uint4*)dh + j) = bh[j];
            *((uint4*)dl + j) = bl[j];
        }
    }
    __syncthreads();

    int wm = wid >> 1;
    int wn = wid & 1;
    uint32_t aBase = sb + OFF_AHI +
        (uint32_t)(((wm * 32 + (lane & 7) + ((lane >> 3) & 1) * 8) * LDS_STRIDE +
                    ((lane >> 4) << 3)) * 2);
    uint32_t aBase1 = aBase + 16 * LDS_STRIDE * 2;
    uint32_t bBase = sb + OFF_BHI +
        (uint32_t)((((lane & 7) + ((lane >> 3) & 1) * 8) * LDS_STRIDE +
                    wn * 64 + ((lane >> 4) << 3)) * 2);

    float acc[2][8][4];
#pragma unroll
    for (int mt = 0; mt < 2; mt++)
#pragma unroll
        for (int nt = 0; nt < 8; nt++)
#pragma unroll
            for (int i = 0; i < 4; i++) acc[mt][nt][i] = 0.0f;

#pragma unroll 1
    for (int p = 0; p < 3; p++) {
        uint32_t aOff = (p == 1) ? (uint32_t)TILE_BYTES : 0u;
        uint32_t bOff = (p == 2) ? (uint32_t)TILE_BYTES : 0u;
#pragma unroll 1
        for (int kk = 0; kk < 8; kk++) {
            uint32_t a0[4], a1[4];
            ldsm_x4(a0, aBase + aOff + kk * 32);
            ldsm_x4(a1, aBase1 + aOff + kk * 32);
#pragma unroll
            for (int g = 0; g < 4; g++) {
                uint32_t b[4];
                ldsm_x4t(b, bBase + bOff + kk * (16 * LDS_STRIDE * 2) + g * 32);
                mma16816(acc[0][2 * g],     a0, b[0], b[1]);
                mma16816(acc[0][2 * g + 1], a0, b[2], b[3]);
                mma16816(acc[1][2 * g],     a1, b[0], b[1]);
                mma16816(acc[1][2 * g + 1], a1, b[2], b[3]);
            }
        }
    }

    // --- Epilogue: scale by dis[row], convert fp16, store half2 pairs ---
#pragma unroll
    for (int mt = 0; mt < 2; mt++) {
        int r0 = row0 + wm * 32 + mt * 16 + (lane >> 2);
        int r1 = r0 + 8;
        float dis0 = (r0 < n) ? rsqrtf((float)(g_degi[r0] + 1)) : 0.0f;
        float dis1 = (r1 < n) ? rsqrtf((float)(g_degi[r1] + 1)) : 0.0f;
        int colb = wn * 64 + (lane & 3) * 2;
#pragma unroll
        for (int nt = 0; nt < 8; nt++) {
            int col = colb + nt * 8;
            if (r0 < n)
                *(__half2*)(g_uh + (size_t)r0 * DF + col) =
                    __floats2half2_rn(acc[mt][nt][0] * dis0, acc[mt][nt][1] * dis0);
            if (r1 < n)
                *(__half2*)(g_uh + (size_t)r1 * DF + col) =
                    __floats2half2_rn(acc[mt][nt][2] * dis1, acc[mt][nt][3] * dis1);
        }
    }
}

// ---------------------------------------------------------------------------
// Fused: agg = u[node] + sum u[csr]; h = relu(dis*agg + b1); w = dis*(h.W2)
// One warp per node, 2 edges in flight (16 lanes x 8 features each, fp16).
__global__ __launch_bounds__(256) void k_agg1(const float* __restrict__ b1,
                                              const float* __restrict__ W2,
                                              int n) {
    int node = (int)((blockIdx.x * (unsigned)blockDim.x + threadIdx.x) >> 5);
    int lane = threadIdx.x & 31;
    if (node >= n) return;
    int half  = lane >> 4;       // which of the 2 in-flight edges
    int lane8 = lane & 15;       // feature slice: 8 features at lane8*8

    int row  = g_rowptr[node];
    int degv = g_degi[node];

    float acc[8];
    // self-loop term: only half 0 (otherwise double-counted after combine)
    {
        uint4 v = (half == 0)
            ? *(const uint4*)(g_uh + (size_t)node * DF + lane8 * 8)
            : make_uint4(0u, 0u, 0u, 0u);
        float2 f0 = __half22float2(*(const __half2*)&v.x);
        float2 f1 = __half22float2(*(const __half2*)&v.y);
        float2 f2 = __half22float2(*(const __half2*)&v.z);
        float2 f3 = __half22float2(*(const __half2*)&v.w);
        acc[0] = f0.x; acc[1] = f0.y; acc[2] = f1.x; acc[3] = f1.y;
        acc[4] = f2.x; acc[5] = f2.y; acc[6] = f3.x; acc[7] = f3.y;
    }

    for (int base = 0; base < degv; base += 32) {
        int e = base + lane;
        int sv = (e < degv) ? g_csr[row + e] : 0;
        int m = degv - base;
        if (m > 32) m = 32;
#pragma unroll 4
        for (int j = 0; j < m; j += 2) {
            int idx = j + half;
            int s = __shfl_sync(0xffffffffu, sv, idx);
            if (idx < m) {
                uint4 v = *(const uint4*)(g_uh + (size_t)s * DF + lane8 * 8);
                float2 f0 = __half22float2(*(const __half2*)&v.x);
                float2 f1 = __half22float2(*(const __half2*)&v.y);
                float2 f2 = __half22float2(*(const __half2*)&v.z);
                float2 f3 = __half22float2(*(const __half2*)&v.w);
                acc[0] += f0.x; acc[1] += f0.y; acc[2] += f1.x; acc[3] += f1.y;
                acc[4] += f2.x; acc[5] += f2.y; acc[6] += f3.x; acc[7] += f3.y;
            }
        }
    }

    // combine the two half-warps (feature-aligned lanes lane8 and lane8+16)
#pragma unroll
    for (int i = 0; i < 8; i++)
        acc[i] += __shfl_xor_sync(0xffffffffu, acc[i], 16);

    float dis = rsqrtf((float)(degv + 1));
    const float4* b1p = (const float4*)(b1 + lane8 * 8);
    const float4* w2p = (const float4*)(W2 + lane8 * 8);
    float4 ba = __ldg(b1p), bbv = __ldg(b1p + 1);
    float4 wa = __ldg(w2p), wb = __ldg(w2p + 1);
    float bv[8] = {ba.x, ba.y, ba.z, ba.w, bbv.x, bbv.y, bbv.z, bbv.w};
    float wv[8] = {wa.x, wa.y, wa.z, wa.w, wb.x, wb.y, wb.z, wb.w};
    float part = 0.0f;
#pragma unroll
    for (int i = 0; i < 8; i++) {
        float h = fmaxf(fmaf(dis, acc[i], bv[i]), 0.0f);
        part = fmaf(h, wv[i], part);
    }
    // reduce within each 16-lane group (halves hold identical data)
#pragma unroll
    for (int o = 8; o; o >>= 1) part += __shfl_xor_sync(0xffffffffu, part, o);
    if (lane == 0) g_w[node] = dis * part;
}

// ---------------------------------------------------------------------------
// Fused layer-2 aggregation + bias
__global__ __launch_bounds__(256) void k_agg2(const float* __restrict__ b2,
                                              float* __restrict__ out, int n) {
    int node = (int)((blockIdx.x * (unsigned)blockDim.x + threadIdx.x) >> 5);
    int lane = threadIdx.x & 31;
    if (node >= n) return;

    int row  = g_rowptr[node];
    int degv = g_degi[node];

    float part = 0.0f;
    for (int e = lane; e < degv; e += 32) part += g_w[g_csr[row + e]];
#pragma unroll
    for (int o = 16; o; o >>= 1) part += __shfl_xor_sync(0xffffffffu, part, o);

    if (lane == 0) {
        float dis = rsqrtf((float)(degv + 1));
        out[node] = fmaf(dis, g_w[node] + part, b2[0]);
    }
}

// ---------------------------------------------------------------------------
extern "C" void kernel_launch(void* const* d_in, const int* in_sizes, int n_in,
                              void* d_out, int out_size) {
    const float* x  = (const float*)d_in[0];
    const int*   ei = (const int*)d_in[1];
    const float* W1 = (const float*)d_in[2];
    const float* b1 = (const float*)d_in[3];
    const float* W2 = (const float*)d_in[4];
    const float* b2 = (const float*)d_in[5];
    float* out = (float*)d_out;

    int n = in_sizes[0] / DF;
    int E = in_sizes[1] / 2;
    const int* src = ei;
    const int* dst = ei + E;

    int nb = (n + 511) / 512;

    cudaFuncSetAttribute(k_gemm_u, cudaFuncAttributeMaxDynamicSharedMemorySize,
                         GSMEM_TOTAL);

    k_zero_deg<<<(n + 255) / 256, 256>>>(n);
    k_count<<<(E + 255) / 256, 256>>>(dst, E);
    k_scanA<<<nb, 512>>>(n);
    k_scanB<<<1, 256>>>(nb);
    k_scanC<<<(n + 255) / 256, 256>>>(n);
    k_fill<<<(E + 255) / 256, 256>>>(src, dst, E);

    k_prep_w<<<(DF * DF + 255) / 256, 256>>>(W1);
    k_gemm_u<<<(n + 127) / 128, 256, GSMEM_TOTAL>>>(x, n);

    {
        long long threads = (long long)n * 32;
        int blocks = (int)((threads + 255) / 256);
        k_agg1<<<blocks, 256>>>(b1, W2, n);
        k_agg2<<<blocks, 256>>>(b2, out, n);
    }
}

// round 9
// speedup vs baseline: 2.2260x; 1.0877x over previous
#include <cuda_runtime.h>
#include <cuda_bf16.h>
#include <cuda_fp16.h>
#include <cstdint>

// Problem shape: N=100000 nodes, D=128 features, E<=1.6M edges.
#define MAXN 100352
#define MAXE 1605632
#define DF   128

// Scratch (device globals: no allocation allowed in kernel_launch)
struct Hdr { int base; int degi[MAXN]; };   // one memset covers base + degrees
__device__ Hdr    g_h;
__device__ int    g_rowptr[MAXN];      // exclusive prefix of degi
__device__ int    g_cursor[MAXN];      // fill cursors
__device__ int    g_csr[MAXE];         // src ids sorted by dst
__device__ __half g_uh[MAXN * DF];     // u = dis * (x @ W1)  (fp16)
__device__ float  g_w[MAXN];           // layer-2 per-node scalar w = dis*(h . W2)

// ---------------------------------------------------------------------------
// mma.sync / ldmatrix helpers (portable sm_80+ PTX)
__device__ __forceinline__ uint32_t smem_to_u32(const void* p) {
    uint32_t a;
    asm("{ .reg .u64 t; cvta.to.shared.u64 t, %1; cvt.u32.u64 %0, t; }"
        : "=r"(a) : "l"(p));
    return a;
}
__device__ __forceinline__ void ldsm_x4(uint32_t* r, uint32_t addr) {
    asm volatile("ldmatrix.sync.aligned.m8n8.x4.shared.b16 {%0,%1,%2,%3}, [%4];"
                 : "=r"(r[0]), "=r"(r[1]), "=r"(r[2]), "=r"(r[3]) : "r"(addr));
}
__device__ __forceinline__ void ldsm_x4t(uint32_t* r, uint32_t addr) {
    asm volatile("ldmatrix.sync.aligned.m8n8.x4.trans.shared.b16 {%0,%1,%2,%3}, [%4];"
                 : "=r"(r[0]), "=r"(r[1]), "=r"(r[2]), "=r"(r[3]) : "r"(addr));
}
__device__ __forceinline__ void mma16816(float* c, const uint32_t* a,
                                         uint32_t b0, uint32_t b1) {
    asm volatile(
        "mma.sync.aligned.m16n8k16.row.col.f32.bf16.bf16.f32 "
        "{%0,%1,%2,%3}, {%4,%5,%6,%7}, {%8,%9}, {%0,%1,%2,%3};"
        : "+f"(c[0]), "+f"(c[1]), "+f"(c[2]), "+f"(c[3])
        : "r"(a[0]), "r"(a[1]), "r"(a[2]), "r"(a[3]), "r"(b0), "r"(b1));
}

// SMEM layout for the GEMM (bf16, padded stride 136 elems)
#define LDS_STRIDE 136
#define TILE_BYTES (128 * LDS_STRIDE * 2)   // 34816
#define OFF_AHI 0
#define OFF_ALO TILE_BYTES
#define OFF_BHI (2 * TILE_BYTES)
#define OFF_BLO (3 * TILE_BYTES)
#define GSMEM_TOTAL (4 * TILE_BYTES)        // 139264

// ---------------------------------------------------------------------------
// CSR build
__global__ void k_count(const int* __restrict__ dst, int E) {
    int e = blockIdx.x * blockDim.x + threadIdx.x;
    if (e < E) atomicAdd(&g_h.degi[dst[e]], 1);
}

// Fused scan: block-local exclusive scan + atomic base assignment (1 kernel).
__global__ __launch_bounds__(512) void k_scanfuse(int n) {
    __shared__ int s[512];
    __shared__ int sbase;
    int i = blockIdx.x * 512 + threadIdx.x;
    int v = (i < n) ? g_h.degi[i] : 0;
    s[threadIdx.x] = v;
    __syncthreads();
#pragma unroll
    for (int o = 1; o < 512; o <<= 1) {
        int t = (threadIdx.x >= o) ? s[threadIdx.x - o] : 0;
        __syncthreads();
        s[threadIdx.x] += t;
        __syncthreads();
    }
    if (threadIdx.x == 511) sbase = atomicAdd(&g_h.base, s[511]);
    __syncthreads();
    if (i < n) {
        int r = sbase + s[threadIdx.x] - v;
        g_rowptr[i] = r;
        g_cursor[i] = r;
    }
}

__global__ void k_fill(const int* __restrict__ src, const int* __restrict__ dst,
                       int E) {
    int e = blockIdx.x * blockDim.x + threadIdx.x;
    if (e < E) {
        int pos = atomicAdd(&g_cursor[dst[e]], 1);
        g_csr[pos] = src[e];
    }
}

// ---------------------------------------------------------------------------
// u = dis * (x @ W1) via split-bf16 mma.sync (3 products, fp32 accum),
// epilogue stores fp16. CTA: 128 rows, 256 threads / 8 warps (4x2).
// W1 converted from fp32 to bf16 hi/lo inline per CTA (no prep kernel).
__global__ __launch_bounds__(256) void k_gemm_u(const float* __restrict__ x,
                                                const float* __restrict__ W1,
                                                int n) {
    extern __shared__ char smem[];
    uint32_t sb = smem_to_u32(smem);
    int tid = threadIdx.x;
    int lane = tid & 31;
    int wid = tid >> 5;
    int row0 = blockIdx.x * 128;

    // --- Stage A: x rows -> bf16 hi/lo into SMEM [m][136]
    {
        int r = tid >> 1;
        int half = tid & 1;
        int row = row0 + r;
        bool rv = row < n;
        const float4* xr = (const float4*)(x + (size_t)row * DF) + half * 16;
        char* ah = smem + OFF_AHI + (size_t)(r * LDS_STRIDE + half * 64) * 2;
        char* al = smem + OFF_ALO + (size_t)(r * LDS_STRIDE + half * 64) * 2;
#pragma unroll
        for (int j = 0; j < 16; j++) {
            float4 v = rv ? xr[j] : make_float4(0.f, 0.f, 0.f, 0.f);
            __nv_bfloat16 h0 = __float2bfloat16(v.x);
            __nv_bfloat16 h1 = __float2bfloat16(v.y);
            __nv_bfloat16 h2 = __float2bfloat16(v.z);
            __nv_bfloat16 h3 = __float2bfloat16(v.w);
            uint32_t hp0 = (uint32_t)__bfloat16_as_ushort(h0) |
                           ((uint32_t)__bfloat16_as_ushort(h1) << 16);
            uint32_t hp1 = (uint32_t)__bfloat16_as_ushort(h2) |
                           ((uint32_t)__bfloat16_as_ushort(h3) << 16);
            __nv_bfloat16 l0 = __float2bfloat16(v.x - __bfloat162float(h0));
            __nv_bfloat16 l1 = __float2bfloat16(v.y - __bfloat162float(h1));
            __nv_bfloat16 l2 = __float2bfloat16(v.z - __bfloat162float(h2));
            __nv_bfloat16 l3 = __float2bfloat16(v.w - __bfloat162float(h3));
            uint32_t lp0 = (uint32_t)__bfloat16_as_ushort(l0) |
                           ((uint32_t)__bfloat16_as_ushort(l1) << 16);
            uint32_t lp1 = (uint32_t)__bfloat16_as_ushort(l2) |
                           ((uint32_t)__bfloat16_as_ushort(l3) << 16);
            *(uint2*)(ah + j * 8) = make_uint2(hp0, hp1);
            *(uint2*)(al + j * 8) = make_uint2(lp0, lp1);
        }
    }
    // --- Stage B: W1 fp32 -> bf16 hi/lo into SMEM [k][136] (inline convert)
    {
        int k = tid >> 1;
        int half = tid & 1;
        const float4* wr = (const float4*)(W1 + (size_t)k * DF) + half * 16;
        char* dh = smem + OFF_BHI + (size_t)(k * LDS_STRIDE + half * 64) * 2;
        char* dl = smem + OFF_BLO + (size_t)(k * LDS_STRIDE + half * 64) * 2;
#pragma unroll
        for (int j = 0; j < 16; j++) {
            float4 v = wr[j];
            __nv_bfloat16 h0 = __float2bfloat16(v.x);
            __nv_bfloat16 h1 = __float2bfloat16(v.y);
            __nv_bfloat16 h2 = __float2bfloat16(v.z);
            __nv_bfloat16 h3 = __float2bfloat16(v.w);
            uint32_t hp0 = (uint32_t)__bfloat16_as_ushort(h0) |
                           ((uint32_t)__bfloat16_as_ushort(h1) << 16);
            uint32_t hp1 = (uint32_t)__bfloat16_as_ushort(h2) |
                           ((uint32_t)__bfloat16_as_ushort(h3) << 16);
            __nv_bfloat16 l0 = __float2bfloat16(v.x - __bfloat162float(h0));
            __nv_bfloat16 l1 = __float2bfloat16(v.y - __bfloat162float(h1));
            __nv_bfloat16 l2 = __float2bfloat16(v.z - __bfloat162float(h2));
            __nv_bfloat16 l3 = __float2bfloat16(v.w - __bfloat162float(h3));
            uint32_t lp0 = (uint32_t)__bfloat16_as_ushort(l0) |
                           ((uint32_t)__bfloat16_as_ushort(l1) << 16);
            uint32_t lp1 = (uint32_t)__bfloat16_as_ushort(l2) |
                           ((uint32_t)__bfloat16_as_ushort(l3) << 16);
            *(uint2*)(dh + j * 8) = make_uint2(hp0, hp1);
            *(uint2*)(dl + j * 8) = make_uint2(lp0, lp1);
        }
    }
    __syncthreads();

    int wm = wid >> 1;
    int wn = wid & 1;
    uint32_t aBase = sb + OFF_AHI +
        (uint32_t)(((wm * 32 + (lane & 7) + ((lane >> 3) & 1) * 8) * LDS_STRIDE +
                    ((lane >> 4) << 3)) * 2);
    uint32_t aBase1 = aBase + 16 * LDS_STRIDE * 2;
    uint32_t bBase = sb + OFF_BHI +
        (uint32_t)((((lane & 7) + ((lane >> 3) & 1) * 8) * LDS_STRIDE +
                    wn * 64 + ((lane >> 4) << 3)) * 2);

    float acc[2][8][4];
#pragma unroll
    for (int mt = 0; mt < 2; mt++)
#pragma unroll
        for (int nt = 0; nt < 8; nt++)
#pragma unroll
            for (int i = 0; i < 4; i++) acc[mt][nt][i] = 0.0f;

#pragma unroll 1
    for (int p = 0; p < 3; p++) {
        uint32_t aOff = (p == 1) ? (uint32_t)TILE_BYTES : 0u;
        uint32_t bOff = (p == 2) ? (uint32_t)TILE_BYTES : 0u;
#pragma unroll 1
        for (int kk = 0; kk < 8; kk++) {
            uint32_t a0[4], a1[4];
            ldsm_x4(a0, aBase + aOff + kk * 32);
            ldsm_x4(a1, aBase1 + aOff + kk * 32);
#pragma unroll
            for (int g = 0; g < 4; g++) {
                uint32_t b[4];
                ldsm_x4t(b, bBase + bOff + kk * (16 * LDS_STRIDE * 2) + g * 32);
                mma16816(acc[0][2 * g],     a0, b[0], b[1]);
                mma16816(acc[0][2 * g + 1], a0, b[2], b[3]);
                mma16816(acc[1][2 * g],     a1, b[0], b[1]);
                mma16816(acc[1][2 * g + 1], a1, b[2], b[3]);
            }
        }
    }

    // --- Epilogue: scale by dis[row], convert fp16, store half2 pairs ---
#pragma unroll
    for (int mt = 0; mt < 2; mt++) {
        int r0 = row0 + wm * 32 + mt * 16 + (lane >> 2);
        int r1 = r0 + 8;
        float dis0 = (r0 < n) ? rsqrtf((float)(g_h.degi[r0] + 1)) : 0.0f;
        float dis1 = (r1 < n) ? rsqrtf((float)(g_h.degi[r1] + 1)) : 0.0f;
        int colb = wn * 64 + (lane & 3) * 2;
#pragma unroll
        for (int nt = 0; nt < 8; nt++) {
            int col = colb + nt * 8;
            if (r0 < n)
                *(__half2*)(g_uh + (size_t)r0 * DF + col) =
                    __floats2half2_rn(acc[mt][nt][0] * dis0, acc[mt][nt][1] * dis0);
            if (r1 < n)
                *(__half2*)(g_uh + (size_t)r1 * DF + col) =
                    __floats2half2_rn(acc[mt][nt][2] * dis1, acc[mt][nt][3] * dis1);
        }
    }
}

// ---------------------------------------------------------------------------
// Fused: agg = u[node] + sum u[csr]; h = relu(dis*agg + b1); w = dis*(h.W2)
// One warp per node, 2 edges in flight (16 lanes x 8 features each, fp16).
__global__ __launch_bounds__(256) void k_agg1(const float* __restrict__ b1,
                                              const float* __restrict__ W2,
                                              int n) {
    int node = (int)((blockIdx.x * (unsigned)blockDim.x + threadIdx.x) >> 5);
    int lane = threadIdx.x & 31;
    if (node >= n) return;
    int half  = lane >> 4;
    int lane8 = lane & 15;

    int row  = g_rowptr[node];
    int degv = g_h.degi[node];

    float acc[8];
    {
        uint4 v = (half == 0)
            ? *(const uint4*)(g_uh + (size_t)node * DF + lane8 * 8)
            : make_uint4(0u, 0u, 0u, 0u);
        float2 f0 = __half22float2(*(const __half2*)&v.x);
        float2 f1 = __half22float2(*(const __half2*)&v.y);
        float2 f2 = __half22float2(*(const __half2*)&v.z);
        float2 f3 = __half22float2(*(const __half2*)&v.w);
        acc[0] = f0.x; acc[1] = f0.y; acc[2] = f1.x; acc[3] = f1.y;
        acc[4] = f2.x; acc[5] = f2.y; acc[6] = f3.x; acc[7] = f3.y;
    }

    for (int base = 0; base < degv; base += 32) {
        int e = base + lane;
        int sv = (e < degv) ? g_csr[row + e] : 0;
        int m = degv - base;
        if (m > 32) m = 32;
#pragma unroll 4
        for (int j = 0; j < m; j += 2) {
            int idx = j + half;
            int s = __shfl_sync(0xffffffffu, sv, idx);
            if (idx < m) {
                uint4 v = *(const uint4*)(g_uh + (size_t)s * DF + lane8 * 8);
                float2 f0 = __half22float2(*(const __half2*)&v.x);
                float2 f1 = __half22float2(*(const __half2*)&v.y);
                float2 f2 = __half22float2(*(const __half2*)&v.z);
                float2 f3 = __half22float2(*(const __half2*)&v.w);
                acc[0] += f0.x; acc[1] += f0.y; acc[2] += f1.x; acc[3] += f1.y;
                acc[4] += f2.x; acc[5] += f2.y; acc[6] += f3.x; acc[7] += f3.y;
            }
        }
    }

#pragma unroll
    for (int i = 0; i < 8; i++)
        acc[i] += __shfl_xor_sync(0xffffffffu, acc[i], 16);

    float dis = rsqrtf((float)(degv + 1));
    const float4* b1p = (const float4*)(b1 + lane8 * 8);
    const float4* w2p = (const float4*)(W2 + lane8 * 8);
    float4 ba = __ldg(b1p), bbv = __ldg(b1p + 1);
    float4 wa = __ldg(w2p), wb = __ldg(w2p + 1);
    float bv[8] = {ba.x, ba.y, ba.z, ba.w, bbv.x, bbv.y, bbv.z, bbv.w};
    float wv[8] = {wa.x, wa.y, wa.z, wa.w, wb.x, wb.y, wb.z, wb.w};
    float part = 0.0f;
#pragma unroll
    for (int i = 0; i < 8; i++) {
        float h = fmaxf(fmaf(dis, acc[i], bv[i]), 0.0f);
        part = fmaf(h, wv[i], part);
    }
#pragma unroll
    for (int o = 8; o; o >>= 1) part += __shfl_xor_sync(0xffffffffu, part, o);
    if (lane == 0) g_w[node] = dis * part;
}

// ---------------------------------------------------------------------------
// Fused layer-2 aggregation + bias
__global__ __launch_bounds__(256) void k_agg2(const float* __restrict__ b2,
                                              float* __restrict__ out, int n) {
    int node = (int)((blockIdx.x * (unsigned)blockDim.x + threadIdx.x) >> 5);
    int lane = threadIdx.x & 31;
    if (node >= n) return;

    int row  = g_rowptr[node];
    int degv = g_h.degi[node];

    float part = 0.0f;
    for (int e = lane; e < degv; e += 32) part += g_w[g_csr[row + e]];
#pragma unroll
    for (int o = 16; o; o >>= 1) part += __shfl_xor_sync(0xffffffffu, part, o);

    if (lane == 0) {
        float dis = rsqrtf((float)(degv + 1));
        out[node] = fmaf(dis, g_w[node] + part, b2[0]);
    }
}

// ---------------------------------------------------------------------------
extern "C" void kernel_launch(void* const* d_in, const int* in_sizes, int n_in,
                              void* d_out, int out_size) {
    const float* x  = (const float*)d_in[0];
    const int*   ei = (const int*)d_in[1];
    const float* W1 = (const float*)d_in[2];
    const float* b1 = (const float*)d_in[3];
    const float* W2 = (const float*)d_in[4];
    const float* b2 = (const float*)d_in[5];
    float* out = (float*)d_out;

    int n = in_sizes[0] / DF;
    int E = in_sizes[1] / 2;
    const int* src = ei;
    const int* dst = ei + E;

    int nb = (n + 511) / 512;

    cudaFuncSetAttribute(k_gemm_u, cudaFuncAttributeMaxDynamicSharedMemorySize,
                         GSMEM_TOTAL);

    // Side stream + events for the fork (created per call; never destroyed —
    // destroying capture-participating streams/events mid-capture is illegal).
    cudaStream_t s2;
    cudaStreamCreateWithFlags(&s2, cudaStreamNonBlocking);
    cudaEvent_t e1, e2;
    cudaEventCreateWithFlags(&e1, cudaEventDisableTiming);
    cudaEventCreateWithFlags(&e2, cudaEventDisableTiming);

    void* hp = nullptr;
    cudaGetSymbolAddress(&hp, g_h);

    // Main chain: zero (memset) -> count -> [fork] -> scanfuse -> fill
    cudaMemsetAsync(hp, 0, sizeof(int) * (MAXN + 1), 0);
    k_count<<<(E + 255) / 256, 256>>>(dst, E);
    cudaEventRecord(e1, 0);

    // Side chain: GEMM (needs only degrees, for the dis epilogue scale)
    cudaStreamWaitEvent(s2, e1, 0);
    k_gemm_u<<<(n + 127) / 128, 256, GSMEM_TOTAL, s2>>>(x, W1, n);
    cudaEventRecord(e2, s2);

    k_scanfuse<<<nb, 512>>>(n);
    k_fill<<<(E + 255) / 256, 256>>>(src, dst, E);

    // Join: aggregation needs both CSR and u
    cudaStreamWaitEvent(0, e2, 0);
    {
        long long threads = (long long)n * 32;
        int blocks = (int)((threads + 255) / 256);
        k_agg1<<<blocks, 256>>>(b1, W2, n);
        k_agg2<<<blocks, 256>>>(b2, out, n);
    }
}